// round 11
// baseline (speedup 1.0000x reference)
#include <cuda_runtime.h>
#include <cuda_bf16.h>
#include <cstdint>

#define BB 32
#define NN 1024
#define DD 512
#define BN (BB * NN)          // 32768 rows
#define OUT_ELEMS (BN * DD)   // 16777216
#define LN_EPS 1e-5f

// ---------------------------------------------------------------------------
// Device scratch (allocation-free rule). Referenced ONLY from device code.
__device__ __align__(128) __nv_bfloat16 g_adj_h[(size_t)BB * NN * NN];
__device__ __align__(128) __nv_bfloat16 g_adj_l[(size_t)BB * NN * NN];
__device__ __align__(128) __nv_bfloat16 g_Xt_h[(size_t)BB * DD * NN];   // [b][512 n][1024 k]
__device__ __align__(128) __nv_bfloat16 g_Xt_l[(size_t)BB * DD * NN];
__device__ __align__(128) __nv_bfloat16 g_S_h[(size_t)BN * DD];
__device__ __align__(128) __nv_bfloat16 g_S_l[(size_t)BN * DD];
__device__ __align__(128) __nv_bfloat16 g_W_h[DD * DD];
__device__ __align__(128) __nv_bfloat16 g_W_l[DD * DD];
__device__ __align__(128) float g_X[(size_t)BN * DD];
__device__ float g_denom[BN];
__device__ float g_mask[BN];

// ---------------------------------------------------------------------------
__device__ __forceinline__ uint32_t smem_u32(const void* p) {
    uint32_t a;
    asm("{ .reg .u64 t; cvta.to.shared.u64 t, %1; cvt.u32.u64 %0, t; }" : "=r"(a) : "l"(p));
    return a;
}

__device__ __forceinline__ void ldsm_x4(uint32_t* r, uint32_t addr) {
    asm volatile("ldmatrix.sync.aligned.m8n8.x4.shared.b16 {%0,%1,%2,%3}, [%4];"
                 : "=r"(r[0]), "=r"(r[1]), "=r"(r[2]), "=r"(r[3]) : "r"(addr));
}

__device__ __forceinline__ void mma16816(float* c, const uint32_t* a, const uint32_t* b) {
    asm volatile(
        "mma.sync.aligned.m16n8k16.row.col.f32.bf16.bf16.f32 "
        "{%0,%1,%2,%3}, {%4,%5,%6,%7}, {%8,%9}, {%10,%11,%12,%13};"
        : "=f"(c[0]), "=f"(c[1]), "=f"(c[2]), "=f"(c[3])
        : "r"(a[0]), "r"(a[1]), "r"(a[2]), "r"(a[3]),
          "r"(b[0]), "r"(b[1]),
          "f"(c[0]), "f"(c[1]), "f"(c[2]), "f"(c[3]));
}

__device__ __forceinline__ void cp16(uint32_t sdst, const void* gsrc) {
    asm volatile("cp.async.cg.shared.global [%0], [%1], 16;" :: "r"(sdst), "l"(gsrc));
}
__device__ __forceinline__ void cp_commit() {
    asm volatile("cp.async.commit_group;" ::: "memory");
}
__device__ __forceinline__ void cp_wait1() {
    asm volatile("cp.async.wait_group 1;" ::: "memory");
}
__device__ __forceinline__ void cp_wait0() {
    asm volatile("cp.async.wait_group 0;" ::: "memory");
}

__device__ __forceinline__ void split2(float v0, float v1, uint32_t& hp, uint32_t& lp) {
    __nv_bfloat16 h0 = __float2bfloat16(v0);
    __nv_bfloat16 h1 = __float2bfloat16(v1);
    __nv_bfloat16 l0 = __float2bfloat16(v0 - __bfloat162float(h0));
    __nv_bfloat16 l1 = __float2bfloat16(v1 - __bfloat162float(h1));
    hp = (uint32_t)__bfloat16_as_ushort(h0) | ((uint32_t)__bfloat16_as_ushort(h1) << 16);
    lp = (uint32_t)__bfloat16_as_ushort(l0) | ((uint32_t)__bfloat16_as_ushort(l1) << 16);
}

// ---------------------------------------------------------------------------
// Fused: adj split into g_adj_h/l AND rowsum -> g_denom, g_mask (rowsum stash).
// One block (256 threads) per adj row (1024 floats = 256 float4).
__global__ __launch_bounds__(256)
void splitrow_adj_kernel(const float* __restrict__ adj) {
    int row = blockIdx.x;                 // 0..BN-1
    int t = threadIdx.x;
    size_t base4 = (size_t)row * 256 + t;  // float4 index within adj
    float4 v = ((const float4*)adj)[base4];
    uint2 hv, lv;
    split2(v.x, v.y, hv.x, lv.x);
    split2(v.z, v.w, hv.y, lv.y);
    ((uint2*)g_adj_h)[base4] = hv;
    ((uint2*)g_adj_l)[base4] = lv;

    float s = (v.x + v.y) + (v.z + v.w);
    #pragma unroll
    for (int o = 16; o > 0; o >>= 1) s += __shfl_down_sync(0xffffffffu, s, o);
    __shared__ float sm[8];
    if ((t & 31) == 0) sm[t >> 5] = s;
    __syncthreads();
    if (t == 0) {
        float tot = 0.f;
        #pragma unroll
        for (int w = 0; w < 8; w++) tot += sm[w];
        g_denom[row] = tot + 1.0f;
        g_mask[row]  = tot;
    }
}

// colsum + mask finalize: mask = ((rowsum + colsum) == 0)
__global__ void colsum_mask_kernel(const float* __restrict__ adj) {
    int idx = blockIdx.x * blockDim.x + threadIdx.x;
    if (idx >= BN) return;
    int b = idx >> 10, n = idx & (NN - 1);
    const float* p = adj + (size_t)b * NN * NN + n;
    float c0 = 0.f, c1 = 0.f, c2 = 0.f, c3 = 0.f;
    #pragma unroll 4
    for (int m = 0; m < NN; m += 4) {
        c0 += p[(size_t)(m + 0) * NN];
        c1 += p[(size_t)(m + 1) * NN];
        c2 += p[(size_t)(m + 2) * NN];
        c3 += p[(size_t)(m + 3) * NN];
    }
    float cs = (c0 + c1) + (c2 + c3);
    g_mask[idx] = ((g_mask[idx] + cs) == 0.0f) ? 1.0f : 0.0f;
}

// W f32 -> g_W_h/g_W_l
__global__ void split_W_kernel(const float* __restrict__ in) {
    size_t i = (size_t)blockIdx.x * blockDim.x + threadIdx.x;
    if (i >= (size_t)DD * DD / 4) return;
    float4 v = ((const float4*)in)[i];
    uint2 hv, lv;
    split2(v.x, v.y, hv.x, lv.x);
    split2(v.z, v.w, hv.y, lv.y);
    ((uint2*)g_W_h)[i] = hv;
    ((uint2*)g_W_l)[i] = lv;
}

// X [B][1024 k][512 n] f32 -> g_Xt_h/l [B][512 n][1024 k] bf16 (transpose+split)
__global__ void tsplit_kernel(const float* __restrict__ inExt, int use_internal) {
    const float* in = use_internal ? g_X : inExt;
    __shared__ float tile[32][33];
    int b = blockIdx.z;
    int k0 = blockIdx.x * 32, n0 = blockIdx.y * 32;
    const float* src = in + (size_t)b * NN * DD;
    int tx = threadIdx.x, ty = threadIdx.y;     // (32, 8)
    #pragma unroll
    for (int r = 0; r < 4; r++)
        tile[ty + r * 8][tx] = src[(size_t)(k0 + ty + r * 8) * DD + n0 + tx];
    __syncthreads();
    __nv_bfloat16* oh = g_Xt_h + (size_t)b * DD * NN;
    __nv_bfloat16* ol = g_Xt_l + (size_t)b * DD * NN;
    #pragma unroll
    for (int r = 0; r < 4; r++) {
        int n = n0 + ty + r * 8;
        float v = tile[tx][ty + r * 8];
        __nv_bfloat16 h = __float2bfloat16(v);
        __nv_bfloat16 l = __float2bfloat16(v - __bfloat162float(h));
        oh[(size_t)n * NN + k0 + tx] = h;
        ol[(size_t)n * NN + k0 + tx] = l;
    }
}

// ---------------------------------------------------------------------------
// Unified tensor-core GEMM, bf16 hi/lo 3-pass compensation via mma.sync.
// 3-stage cp.async pipeline, one __syncthreads per K-chunk.
// mode 0 (gemm1): D = adj @ Xt^T ; epilogue S = D + residual -> S_hi/S_lo bf16
// mode 1 (gemm2): D = S @ W^T   ; epilogue g_X = relu((D + 2b)/denom)  f32
#define STRIDE 40
#define ARR_B   (128 * STRIDE * 2)      // bytes per tile array (10240)
#define STAGE_B (4 * ARR_B)             // Ah, Al, Bh, Bl     (40960)
#define NSTAGE  3
#define SMEM_DYN (NSTAGE * STAGE_B)     // 122880

__global__ __launch_bounds__(256, 1)
void mma_gemm_kernel(int mode, const float* __restrict__ resExt, int res_internal,
                     const float* __restrict__ bias) {
    extern __shared__ __align__(16) char smem[];
    const uint32_t sb = smem_u32(smem);

    int tid = threadIdx.x, wid = tid >> 5, lane = tid & 31;
    int wm = (wid >> 2) * 64, wn = (wid & 3) * 32;
    int grp = lane >> 2, qid = lane & 3;

    const int K = (mode == 0) ? NN : DD;
    const int nchunks = K / 32;
    const int b = blockIdx.z;
    const int grow0 = (blockIdx.z * gridDim.y + blockIdx.y) * 128;
    const int col0 = blockIdx.x * 128;

    const __nv_bfloat16 *Ah, *Al, *Bh, *Bl;
    int lda, ldb;
    if (mode == 0) {
        size_t aoff = (size_t)b * NN * NN + (size_t)(blockIdx.y * 128) * NN;
        Ah = g_adj_h + aoff;  Al = g_adj_l + aoff;  lda = NN;
        size_t boff = (size_t)b * DD * NN + (size_t)col0 * NN;
        Bh = g_Xt_h + boff;   Bl = g_Xt_l + boff;   ldb = NN;
    } else {
        size_t aoff = (size_t)grow0 * DD;
        Ah = g_S_h + aoff;    Al = g_S_l + aoff;    lda = DD;
        size_t boff = (size_t)col0 * DD;
        Bh = g_W_h + boff;    Bl = g_W_l + boff;    ldb = DD;
    }

    // staging: thread owns row = tid/2, 16-elem half = tid%2 (two 16B chunks/array)
    const int lrow = tid >> 1;
    const int lcol = (tid & 1) * 16;
    const __nv_bfloat16* gp[4] = {
        Ah + (size_t)lrow * lda + lcol,  Al + (size_t)lrow * lda + lcol,
        Bh + (size_t)lrow * ldb + lcol,  Bl + (size_t)lrow * ldb + lcol };
    const uint32_t sdst0 = (uint32_t)((lrow * STRIDE + lcol) * 2);

    // per-thread ldmatrix base offsets (bytes within a stage)
    const int mat = lane >> 3, rr = lane & 7;
    const uint32_t aOffA = (uint32_t)(((wm + (mat & 1) * 8 + rr) * STRIDE + (mat >> 1) * 8) * 2);
    const uint32_t aOffB = (uint32_t)(((wn + (mat >> 1) * 8 + rr) * STRIDE + (mat & 1) * 8) * 2);

    float acc[4][4][4];
    #pragma unroll
    for (int i = 0; i < 4; i++)
        #pragma unroll
        for (int j = 0; j < 4; j++)
            #pragma unroll
            for (int q = 0; q < 4; q++) acc[i][j][q] = 0.f;

    // prologue: stages 0 and 1 in flight
    #pragma unroll
    for (int s = 0; s < 2; s++) {
        uint32_t sd = sb + s * STAGE_B + sdst0;
        int k0 = s * 32;
        #pragma unroll
        for (int t = 0; t < 4; t++) {
            cp16(sd + t * ARR_B,      gp[t] + k0);
            cp16(sd + t * ARR_B + 16, gp[t] + k0 + 8);
        }
        cp_commit();
    }

    int buf = 0;
    for (int ci = 0; ci < nchunks; ci++) {
        if (ci + 1 < nchunks) cp_wait1(); else cp_wait0();
        __syncthreads();

        // prefetch stage ci+2 into the buffer freed at iter ci-1
        if (ci + 2 < nchunks) {
            int wbuf = buf + 2; if (wbuf >= NSTAGE) wbuf -= NSTAGE;
            uint32_t sd = sb + wbuf * STAGE_B + sdst0;
            int k0 = (ci + 2) * 32;
            #pragma unroll
            for (int t = 0; t < 4; t++) {
                cp16(sd + t * ARR_B,      gp[t] + k0);
                cp16(sd + t * ARR_B + 16, gp[t] + k0 + 8);
            }
            cp_commit();
        }

        const uint32_t stg = sb + buf * STAGE_B;
        const uint32_t bAh = stg + aOffA;
        const uint32_t bAl = stg + ARR_B + aOffA;
        const uint32_t bBh = stg + 2 * ARR_B + aOffB;
        const uint32_t bBl = stg + 3 * ARR_B + aOffB;

        #pragma unroll
        for (int ks = 0; ks < 2; ks++) {
            const uint32_t kof = (uint32_t)(ks * 32);
            uint32_t ah[4][4], al[4][4], bh[8], bl[8];
            #pragma unroll
            for (int mi = 0; mi < 4; mi++) {
                ldsm_x4(ah[mi], bAh + mi * (16 * STRIDE * 2) + kof);
                ldsm_x4(al[mi], bAl + mi * (16 * STRIDE * 2) + kof);
            }
            ldsm_x4(bh,     bBh + kof);
            ldsm_x4(bh + 4, bBh + 16 * STRIDE * 2 + kof);
            ldsm_x4(bl,     bBl + kof);
            ldsm_x4(bl + 4, bBl + 16 * STRIDE * 2 + kof);

            #pragma unroll
            for (int mi = 0; mi < 4; mi++)
                #pragma unroll
                for (int ni = 0; ni < 4; ni++) {
                    mma16816(acc[mi][ni], ah[mi], &bh[ni * 2]);
                    mma16816(acc[mi][ni], ah[mi], &bl[ni * 2]);
                    mma16816(acc[mi][ni], al[mi], &bh[ni * 2]);
                }
        }
        buf++; if (buf == NSTAGE) buf = 0;
    }

    // Epilogue. Thread owns (rows grp, grp+8) x (cols qid*2, +1) per (mi,ni) tile.
    #pragma unroll
    for (int mi = 0; mi < 4; mi++) {
        #pragma unroll
        for (int h = 0; h < 2; h++) {
            int grow = grow0 + wm + mi * 16 + grp + h * 8;
            if (mode == 0) {
                const float* rbase = res_internal ? g_X : resExt;
                #pragma unroll
                for (int ni = 0; ni < 4; ni++) {
                    int gcol = col0 + wn + ni * 8 + qid * 2;
                    float2 res = *(const float2*)&rbase[(size_t)grow * DD + gcol];
                    uint32_t hp, lp;
                    split2(acc[mi][ni][h * 2 + 0] + res.x,
                           acc[mi][ni][h * 2 + 1] + res.y, hp, lp);
                    *(uint32_t*)&g_S_h[(size_t)grow * DD + gcol] = hp;
                    *(uint32_t*)&g_S_l[(size_t)grow * DD + gcol] = lp;
                }
            } else {
                float rden = 1.0f / g_denom[grow];
                #pragma unroll
                for (int ni = 0; ni < 4; ni++) {
                    int gcol = col0 + wn + ni * 8 + qid * 2;
                    float2 bi = *(const float2*)&bias[gcol];
                    float2 o;
                    o.x = fmaxf((acc[mi][ni][h * 2 + 0] + 2.0f * bi.x) * rden, 0.0f);
                    o.y = fmaxf((acc[mi][ni][h * 2 + 1] + 2.0f * bi.y) * rden, 0.0f);
                    *(float2*)&g_X[(size_t)grow * DD + gcol] = o;
                }
            }
        }
    }
}

// ---------------------------------------------------------------------------
// LayerNorm over last dim (512), one block (128 threads) per row, g_X -> out
__global__ void ln_kernel(const float* __restrict__ gamma,
                          const float* __restrict__ beta,
                          float* __restrict__ out) {
    int row = blockIdx.x;
    int t   = threadIdx.x;
    const float* p = g_X + (size_t)row * DD;
    float4 v = *(const float4*)&p[t * 4];

    __shared__ float sm[4];
    __shared__ float s_mu, s_rstd;

    float s = v.x + v.y + v.z + v.w;
    #pragma unroll
    for (int o = 16; o > 0; o >>= 1) s += __shfl_down_sync(0xffffffffu, s, o);
    if ((t & 31) == 0) sm[t >> 5] = s;
    __syncthreads();
    if (t == 0) s_mu = (sm[0] + sm[1] + sm[2] + sm[3]) * (1.0f / DD);
    __syncthreads();

    float mu = s_mu;
    float dx = v.x - mu, dy = v.y - mu, dz = v.z - mu, dw = v.w - mu;
    float q = dx * dx + dy * dy + dz * dz + dw * dw;
    #pragma unroll
    for (int o = 16; o > 0; o >>= 1) q += __shfl_down_sync(0xffffffffu, q, o);
    if ((t & 31) == 0) sm[t >> 5] = q;
    __syncthreads();
    if (t == 0)
        s_rstd = rsqrtf((sm[0] + sm[1] + sm[2] + sm[3]) * (1.0f / DD) + LN_EPS);
    __syncthreads();

    float r = s_rstd;
    float4 ga = *(const float4*)&gamma[t * 4];
    float4 be = *(const float4*)&beta[t * 4];
    float4 o;
    o.x = dx * r * ga.x + be.x;
    o.y = dy * r * ga.y + be.y;
    o.z = dz * r * ga.z + be.z;
    o.w = dw * r * ga.w + be.w;
    *(float4*)&out[(size_t)row * DD + t * 4] = o;
}

__global__ void mask_out_kernel(float* __restrict__ out, int count) {
    int i = blockIdx.x * blockDim.x + threadIdx.x;
    if (i < count) out[(size_t)OUT_ELEMS + i] = (i < BN) ? g_mask[i] : 0.0f;
}

// ---------------------------------------------------------------------------
extern "C" void kernel_launch(void* const* d_in, const int* in_sizes, int n_in,
                              void* d_out, int out_size) {
    const float* adj = (const float*)d_in[0];
    const float* x0  = (const float*)d_in[1];
    const float* W0w = (const float*)d_in[3];
    const float* W0b = (const float*)d_in[4];
    const float* W1w = (const float*)d_in[5];
    const float* W1b = (const float*)d_in[6];
    const float* lng = (const float*)d_in[7];
    const float* lnb = (const float*)d_in[8];
    float* out = (float*)d_out;

    cudaFuncSetAttribute(mma_gemm_kernel,
                         cudaFuncAttributeMaxDynamicSharedMemorySize, SMEM_DYN);

    // adj split + rowsum fused; colsum finalizes mask
    splitrow_adj_kernel<<<BN, 256>>>(adj);
    colsum_mask_kernel<<<BN / 256, 256>>>(adj);

    dim3 tgrid(NN / 32, DD / 32, BB), tblk(32, 8);
    tsplit_kernel<<<tgrid, tblk>>>(x0, 0);
    split_W_kernel<<<(DD * DD / 4 + 255) / 256, 256>>>(W0w);

    dim3 grid1(DD / 128, NN / 128, BB);     // 4 x 8 x 32
    dim3 grid2(DD / 128, BN / 128, 1);      // 4 x 256

    // Layer 0
    mma_gemm_kernel<<<grid1, 256, SMEM_DYN>>>(0, x0, 0, nullptr);
    mma_gemm_kernel<<<grid2, 256, SMEM_DYN>>>(1, nullptr, 0, W0b);

    // Layer 1
    tsplit_kernel<<<tgrid, tblk>>>(nullptr, 1);
    split_W_kernel<<<(DD * DD / 4 + 255) / 256, 256>>>(W1w);
    mma_gemm_kernel<<<grid1, 256, SMEM_DYN>>>(0, nullptr, 1, nullptr);
    mma_gemm_kernel<<<grid2, 256, SMEM_DYN>>>(1, nullptr, 0, W1b);

    // LayerNorm -> output
    ln_kernel<<<BN, 128>>>(lng, lnb, out);

    int tail = out_size - OUT_ELEMS;
    if (tail > 0)
        mask_out_kernel<<<(tail + 255) / 256, 256>>>(out, tail);
}

// round 14
// speedup vs baseline: 1.2594x; 1.2594x over previous
#include <cuda_runtime.h>
#include <cuda_fp16.h>
#include <cstdint>

#define BB 32
#define NN 1024
#define DD 512
#define BN (BB * NN)          // 32768 rows
#define OUT_ELEMS (BN * DD)   // 16777216
#define LN_EPS 1e-5f
#define L2SCALE 1024.0f       // exact pow2 boost for small layer-2 activations

// ---------------------------------------------------------------------------
// Device scratch (allocation-free rule). Referenced ONLY from device code.
__device__ __align__(128) __half g_adj[(size_t)BB * NN * NN];            // fp16 single
__device__ __align__(128) __half g_Xt_h[(size_t)BB * DD * NN];           // [b][512 n][1024 k]
__device__ __align__(128) __half g_Xt_l[(size_t)BB * DD * NN];
__device__ __align__(128) __half g_S_h[(size_t)BN * DD];
__device__ __align__(128) __half g_S_l[(size_t)BN * DD];
__device__ __align__(128) __half g_W[DD * DD];                           // fp16 single
__device__ __align__(128) float g_X[(size_t)BN * DD];
__device__ float g_denom[BN];
__device__ float g_mask[BN];

// ---------------------------------------------------------------------------
__device__ __forceinline__ uint32_t smem_u32(const void* p) {
    uint32_t a;
    asm("{ .reg .u64 t; cvta.to.shared.u64 t, %1; cvt.u32.u64 %0, t; }" : "=r"(a) : "l"(p));
    return a;
}

__device__ __forceinline__ void ldsm_x4(uint32_t* r, uint32_t addr) {
    asm volatile("ldmatrix.sync.aligned.m8n8.x4.shared.b16 {%0,%1,%2,%3}, [%4];"
                 : "=r"(r[0]), "=r"(r[1]), "=r"(r[2]), "=r"(r[3]) : "r"(addr));
}

// fp16 inputs, fp32 accumulate
__device__ __forceinline__ void mma16816(float* c, const uint32_t* a, const uint32_t* b) {
    asm volatile(
        "mma.sync.aligned.m16n8k16.row.col.f32.f16.f16.f32 "
        "{%0,%1,%2,%3}, {%4,%5,%6,%7}, {%8,%9}, {%10,%11,%12,%13};"
        : "=f"(c[0]), "=f"(c[1]), "=f"(c[2]), "=f"(c[3])
        : "r"(a[0]), "r"(a[1]), "r"(a[2]), "r"(a[3]),
          "r"(b[0]), "r"(b[1]),
          "f"(c[0]), "f"(c[1]), "f"(c[2]), "f"(c[3]));
}

__device__ __forceinline__ uint32_t pack_h2(__half a, __half b) {
    return (uint32_t)__half_as_ushort(a) | ((uint32_t)__half_as_ushort(b) << 16);
}
// fp16 hi/lo split of an fp32 value pair
__device__ __forceinline__ void hsplit2(float v0, float v1, uint32_t& hp, uint32_t& lp) {
    __half h0 = __float2half_rn(v0);
    __half h1 = __float2half_rn(v1);
    __half l0 = __float2half_rn(v0 - __half2float(h0));
    __half l1 = __float2half_rn(v1 - __half2float(h1));
    hp = pack_h2(h0, h1);
    lp = pack_h2(l0, l1);
}

// ---------------------------------------------------------------------------
// Fused: adj -> fp16 plane g_adj AND rowsum -> g_denom (+g_mask stash).
// One block (256 threads) per adj row (1024 floats).
__global__ __launch_bounds__(256)
void splitrow_adj_kernel(const float* __restrict__ adj) {
    int row = blockIdx.x;
    int t = threadIdx.x;
    size_t base4 = (size_t)row * 256 + t;
    float4 v = ((const float4*)adj)[base4];
    uint2 hv;
    hv.x = pack_h2(__float2half_rn(v.x), __float2half_rn(v.y));
    hv.y = pack_h2(__float2half_rn(v.z), __float2half_rn(v.w));
    ((uint2*)g_adj)[base4] = hv;

    float s = (v.x + v.y) + (v.z + v.w);
    #pragma unroll
    for (int o = 16; o > 0; o >>= 1) s += __shfl_down_sync(0xffffffffu, s, o);
    __shared__ float sm[8];
    if ((t & 31) == 0) sm[t >> 5] = s;
    __syncthreads();
    if (t == 0) {
        float tot = 0.f;
        #pragma unroll
        for (int w = 0; w < 8; w++) tot += sm[w];
        g_denom[row] = tot + 1.0f;
        g_mask[row]  = tot;
    }
}

// colsum + mask finalize (only launched when mask is part of the output)
__global__ void colsum_mask_kernel(const float* __restrict__ adj) {
    int idx = blockIdx.x * blockDim.x + threadIdx.x;
    if (idx >= BN) return;
    int b = idx >> 10, n = idx & (NN - 1);
    const float* p = adj + (size_t)b * NN * NN + n;
    float c0 = 0.f, c1 = 0.f, c2 = 0.f, c3 = 0.f;
    #pragma unroll 4
    for (int m = 0; m < NN; m += 4) {
        c0 += p[(size_t)(m + 0) * NN];
        c1 += p[(size_t)(m + 1) * NN];
        c2 += p[(size_t)(m + 2) * NN];
        c3 += p[(size_t)(m + 3) * NN];
    }
    float cs = (c0 + c1) + (c2 + c3);
    g_mask[idx] = ((g_mask[idx] + cs) == 0.0f) ? 1.0f : 0.0f;
}

// W f32 -> g_W fp16 single plane
__global__ void split_W_kernel(const float* __restrict__ in) {
    size_t i = (size_t)blockIdx.x * blockDim.x + threadIdx.x;
    if (i >= (size_t)DD * DD / 4) return;
    float4 v = ((const float4*)in)[i];
    uint2 hv;
    hv.x = pack_h2(__float2half_rn(v.x), __float2half_rn(v.y));
    hv.y = pack_h2(__float2half_rn(v.z), __float2half_rn(v.w));
    ((uint2*)g_W)[i] = hv;
}

// X [B][1024 k][512 n] f32 -> g_Xt_h/l [B][512 n][1024 k] fp16 (transpose+split)
// scale: exact pow2 applied before split (undone in gemm1 epilogue)
__global__ void tsplit_kernel(const float* __restrict__ inExt, int use_internal,
                              float scale) {
    const float* in = use_internal ? g_X : inExt;
    __shared__ float tile[32][33];
    int b = blockIdx.z;
    int k0 = blockIdx.x * 32, n0 = blockIdx.y * 32;
    const float* src = in + (size_t)b * NN * DD;
    int tx = threadIdx.x, ty = threadIdx.y;     // (32, 8)
    #pragma unroll
    for (int r = 0; r < 4; r++)
        tile[ty + r * 8][tx] = src[(size_t)(k0 + ty + r * 8) * DD + n0 + tx];
    __syncthreads();
    __half* oh = g_Xt_h + (size_t)b * DD * NN;
    __half* ol = g_Xt_l + (size_t)b * DD * NN;
    #pragma unroll
    for (int r = 0; r < 4; r++) {
        int n = n0 + ty + r * 8;
        float v = tile[tx][ty + r * 8] * scale;
        __half h = __float2half_rn(v);
        __half l = __float2half_rn(v - __half2float(h));
        oh[(size_t)n * NN + k0 + tx] = h;
        ol[(size_t)n * NN + k0 + tx] = l;
    }
}

// ---------------------------------------------------------------------------
// Unified tensor-core GEMM, fp16 2-pass (X-side hi/lo split, other side single).
// mode 0 (gemm1): D = adj @ (Xh+Xl)^T ; S = D*invscale + res -> S_h/S_l fp16
// mode 1 (gemm2): D = (Sh+Sl) @ W^T   ; g_X = relu((D + 2b)/denom)  f32
// CTA 128x128, K-chunk 32, 8 warps (64x32 warp tile), reg-prefetch staging.
#define STRIDE 40
#define STEP   (16 * STRIDE * 2)    // 1280 bytes per 16-row block

__global__ __launch_bounds__(256, 1)
void mma_gemm_kernel(int mode, const float* __restrict__ resExt, int res_internal,
                     const float* __restrict__ bias, float invscale) {
    __shared__ __align__(16) __half sP [128 * STRIDE];
    __shared__ __align__(16) __half sQh[128 * STRIDE];
    __shared__ __align__(16) __half sQl[128 * STRIDE];

    int tid = threadIdx.x, wid = tid >> 5, lane = tid & 31;
    int wm = (wid >> 2) * 64, wn = (wid & 3) * 32;
    int grp = lane >> 2, qid = lane & 3;

    const int K = (mode == 0) ? NN : DD;
    const int nchunks = K / 32;
    const int b = blockIdx.z;
    const int grow0 = (blockIdx.z * gridDim.y + blockIdx.y) * 128;
    const int col0 = blockIdx.x * 128;

    // P = single-plane operand (adj A-side / W B-side); Q = split operand
    const __half *P, *Qh, *Ql;
    int ld;
    if (mode == 0) {
        P  = g_adj  + (size_t)b * NN * NN + (size_t)(blockIdx.y * 128) * NN;
        Qh = g_Xt_h + (size_t)b * DD * NN + (size_t)col0 * NN;
        Ql = g_Xt_l + (size_t)b * DD * NN + (size_t)col0 * NN;
        ld = NN;
    } else {
        Qh = g_S_h + (size_t)grow0 * DD;
        Ql = g_S_l + (size_t)grow0 * DD;
        P  = g_W + (size_t)col0 * DD;
        ld = DD;
    }

    // staging: thread owns (row = tid/2, 16-half chunk = tid%2)
    const int lrow = tid >> 1;
    const int lcol = (tid & 1) * 16;
    const __half* gp[3] = { P  + (size_t)lrow * ld + lcol,
                            Qh + (size_t)lrow * ld + lcol,
                            Ql + (size_t)lrow * ld + lcol };

    // ldmatrix per-thread offsets (A-role / B-role)
    const int mat = lane >> 3, rr = lane & 7;
    const uint32_t offA = (uint32_t)(((wm + (mat & 1) * 8 + rr) * STRIDE + (mat >> 1) * 8) * 2);
    const uint32_t offB = (uint32_t)(((wn + (mat >> 1) * 8 + rr) * STRIDE + (mat & 1) * 8) * 2);
    const uint32_t sPb  = smem_u32(sP);
    const uint32_t sQhb = smem_u32(sQh);
    const uint32_t sQlb = smem_u32(sQl);

    float acc[4][4][4];
    #pragma unroll
    for (int i = 0; i < 4; i++)
        #pragma unroll
        for (int j = 0; j < 4; j++)
            #pragma unroll
            for (int q = 0; q < 4; q++) acc[i][j][q] = 0.f;

    uint4 p0 = *(const uint4*)gp[0], p1 = *(const uint4*)(gp[0] + 8);
    uint4 p2 = *(const uint4*)gp[1], p3 = *(const uint4*)(gp[1] + 8);
    uint4 p4 = *(const uint4*)gp[2], p5 = *(const uint4*)(gp[2] + 8);

    for (int ci = 0; ci < nchunks; ci++) {
        __syncthreads();
        *(uint4*)&sP [lrow * STRIDE + lcol]     = p0;
        *(uint4*)&sP [lrow * STRIDE + lcol + 8] = p1;
        *(uint4*)&sQh[lrow * STRIDE + lcol]     = p2;
        *(uint4*)&sQh[lrow * STRIDE + lcol + 8] = p3;
        *(uint4*)&sQl[lrow * STRIDE + lcol]     = p4;
        *(uint4*)&sQl[lrow * STRIDE + lcol + 8] = p5;
        __syncthreads();

        if (ci + 1 < nchunks) {
            int k0 = (ci + 1) * 32;
            p0 = *(const uint4*)(gp[0] + k0); p1 = *(const uint4*)(gp[0] + k0 + 8);
            p2 = *(const uint4*)(gp[1] + k0); p3 = *(const uint4*)(gp[1] + k0 + 8);
            p4 = *(const uint4*)(gp[2] + k0); p5 = *(const uint4*)(gp[2] + k0 + 8);
        }

        #pragma unroll
        for (int ks = 0; ks < 2; ks++) {
            const uint32_t kof = (uint32_t)(ks * 32);
            if (mode == 0) {
                // A = P (adj), B = Qh/Ql (X split)
                uint32_t a[4][4], bh[8], bl[8];
                #pragma unroll
                for (int mi = 0; mi < 4; mi++)
                    ldsm_x4(a[mi], sPb + offA + mi * STEP + kof);
                ldsm_x4(bh,     sQhb + offB + kof);
                ldsm_x4(bh + 4, sQhb + offB + STEP + kof);
                ldsm_x4(bl,     sQlb + offB + kof);
                ldsm_x4(bl + 4, sQlb + offB + STEP + kof);
                #pragma unroll
                for (int mi = 0; mi < 4; mi++)
                    #pragma unroll
                    for (int ni = 0; ni < 4; ni++) {
                        mma16816(acc[mi][ni], a[mi], &bh[ni * 2]);
                        mma16816(acc[mi][ni], a[mi], &bl[ni * 2]);
                    }
            } else {
                // A = Qh/Ql (S split), B = P (W)
                uint32_t ah[4][4], al[4][4], bb[8];
                #pragma unroll
                for (int mi = 0; mi < 4; mi++) {
                    ldsm_x4(ah[mi], sQhb + offA + mi * STEP + kof);
                    ldsm_x4(al[mi], sQlb + offA + mi * STEP + kof);
                }
                ldsm_x4(bb,     sPb + offB + kof);
                ldsm_x4(bb + 4, sPb + offB + STEP + kof);
                #pragma unroll
                for (int mi = 0; mi < 4; mi++)
                    #pragma unroll
                    for (int ni = 0; ni < 4; ni++) {
                        mma16816(acc[mi][ni], ah[mi], &bb[ni * 2]);
                        mma16816(acc[mi][ni], al[mi], &bb[ni * 2]);
                    }
            }
        }
    }

    // Epilogue. Thread owns (rows grp, grp+8) x (cols qid*2, +1) per (mi,ni) tile.
    #pragma unroll
    for (int mi = 0; mi < 4; mi++) {
        #pragma unroll
        for (int h = 0; h < 2; h++) {
            int grow = grow0 + wm + mi * 16 + grp + h * 8;
            if (mode == 0) {
                const float* rbase = res_internal ? g_X : resExt;
                #pragma unroll
                for (int ni = 0; ni < 4; ni++) {
                    int gcol = col0 + wn + ni * 8 + qid * 2;
                    float2 res = *(const float2*)&rbase[(size_t)grow * DD + gcol];
                    uint32_t hp, lp;
                    hsplit2(acc[mi][ni][h * 2 + 0] * invscale + res.x,
                            acc[mi][ni][h * 2 + 1] * invscale + res.y, hp, lp);
                    *(uint32_t*)&g_S_h[(size_t)grow * DD + gcol] = hp;
                    *(uint32_t*)&g_S_l[(size_t)grow * DD + gcol] = lp;
                }
            } else {
                float rden = 1.0f / g_denom[grow];
                #pragma unroll
                for (int ni = 0; ni < 4; ni++) {
                    int gcol = col0 + wn + ni * 8 + qid * 2;
                    float2 bi = *(const float2*)&bias[gcol];
                    float2 o;
                    o.x = fmaxf((acc[mi][ni][h * 2 + 0] + 2.0f * bi.x) * rden, 0.0f);
                    o.y = fmaxf((acc[mi][ni][h * 2 + 1] + 2.0f * bi.y) * rden, 0.0f);
                    *(float2*)&g_X[(size_t)grow * DD + gcol] = o;
                }
            }
        }
    }
}

// ---------------------------------------------------------------------------
// LayerNorm over last dim (512), one block (128 threads) per row, g_X -> out
__global__ void ln_kernel(const float* __restrict__ gamma,
                          const float* __restrict__ beta,
                          float* __restrict__ out) {
    int row = blockIdx.x;
    int t   = threadIdx.x;
    const float* p = g_X + (size_t)row * DD;
    float4 v = *(const float4*)&p[t * 4];

    __shared__ float sm[4];
    __shared__ float s_mu, s_rstd;

    float s = v.x + v.y + v.z + v.w;
    #pragma unroll
    for (int o = 16; o > 0; o >>= 1) s += __shfl_down_sync(0xffffffffu, s, o);
    if ((t & 31) == 0) sm[t >> 5] = s;
    __syncthreads();
    if (t == 0) s_mu = (sm[0] + sm[1] + sm[2] + sm[3]) * (1.0f / DD);
    __syncthreads();

    float mu = s_mu;
    float dx = v.x - mu, dy = v.y - mu, dz = v.z - mu, dw = v.w - mu;
    float q = dx * dx + dy * dy + dz * dz + dw * dw;
    #pragma unroll
    for (int o = 16; o > 0; o >>= 1) q += __shfl_down_sync(0xffffffffu, q, o);
    if ((t & 31) == 0) sm[t >> 5] = q;
    __syncthreads();
    if (t == 0)
        s_rstd = rsqrtf((sm[0] + sm[1] + sm[2] + sm[3]) * (1.0f / DD) + LN_EPS);
    __syncthreads();

    float r = s_rstd;
    float4 ga = *(const float4*)&gamma[t * 4];
    float4 be = *(const float4*)&beta[t * 4];
    float4 o;
    o.x = dx * r * ga.x + be.x;
    o.y = dy * r * ga.y + be.y;
    o.z = dz * r * ga.z + be.z;
    o.w = dw * r * ga.w + be.w;
    *(float4*)&out[(size_t)row * DD + t * 4] = o;
}

__global__ void mask_out_kernel(float* __restrict__ out, int count) {
    int i = blockIdx.x * blockDim.x + threadIdx.x;
    if (i < count) out[(size_t)OUT_ELEMS + i] = (i < BN) ? g_mask[i] : 0.0f;
}

// ---------------------------------------------------------------------------
extern "C" void kernel_launch(void* const* d_in, const int* in_sizes, int n_in,
                              void* d_out, int out_size) {
    const float* adj = (const float*)d_in[0];
    const float* x0  = (const float*)d_in[1];
    const float* W0w = (const float*)d_in[3];
    const float* W0b = (const float*)d_in[4];
    const float* W1w = (const float*)d_in[5];
    const float* W1b = (const float*)d_in[6];
    const float* lng = (const float*)d_in[7];
    const float* lnb = (const float*)d_in[8];
    float* out = (float*)d_out;
    int tail = out_size - OUT_ELEMS;

    // adj -> fp16 plane + rowsum/denom
    splitrow_adj_kernel<<<BN, 256>>>(adj);
    if (tail > 0)   // mask only needed when it is part of the output
        colsum_mask_kernel<<<BN / 256, 256>>>(adj);

    dim3 tgrid(NN / 32, DD / 32, BB), tblk(32, 8);
    tsplit_kernel<<<tgrid, tblk>>>(x0, 0, 1.0f);
    split_W_kernel<<<(DD * DD / 4 + 255) / 256, 256>>>(W0w);

    dim3 grid1(DD / 128, NN / 128, BB);     // 4 x 8 x 32
    dim3 grid2(DD / 128, BN / 128, 1);      // 4 x 256

    // Layer 0
    mma_gemm_kernel<<<grid1, 256>>>(0, x0, 0, nullptr, 1.0f);
    mma_gemm_kernel<<<grid2, 256>>>(1, nullptr, 0, W0b, 1.0f);

    // Layer 1 (activations are small: pre-scale by 2^10, undo in epilogue)
    tsplit_kernel<<<tgrid, tblk>>>(nullptr, 1, L2SCALE);
    split_W_kernel<<<(DD * DD / 4 + 255) / 256, 256>>>(W1w);
    mma_gemm_kernel<<<grid1, 256>>>(0, nullptr, 1, nullptr, 1.0f / L2SCALE);
    mma_gemm_kernel<<<grid2, 256>>>(1, nullptr, 0, W1b, 1.0f);

    // LayerNorm -> output
    ln_kernel<<<BN, 128>>>(lng, lnb, out);

    if (tail > 0)
        mask_out_kernel<<<(tail + 255) / 256, 256>>>(out, tail);
}

// round 17
// speedup vs baseline: 1.8699x; 1.4847x over previous
#include <cuda_runtime.h>
#include <cuda_fp16.h>
#include <cstdint>

#define BB 32
#define NN 1024
#define DD 512
#define BN (BB * NN)          // 32768 rows
#define OUT_ELEMS (BN * DD)   // 16777216
#define LN_EPS 1e-5f
#define L2SCALE 1024.0f       // exact pow2 boost for small layer-2 activations

// ---------------------------------------------------------------------------
// Device scratch (allocation-free rule). Referenced ONLY from device code.
__device__ __align__(128) __half g_adj[(size_t)BB * NN * NN];   // fp16 plane
__device__ __align__(128) __half g_Xt [(size_t)BB * DD * NN];   // [b][512 n][1024 k]
__device__ __align__(128) __half g_S  [(size_t)BN * DD];        // Ax + x, fp16
__device__ __align__(128) __half g_W  [DD * DD];                // fp16 plane
__device__ __align__(128) float g_X[(size_t)BN * DD];
__device__ float g_denom[BN];
__device__ float g_mask[BN];

// ---------------------------------------------------------------------------
__device__ __forceinline__ uint32_t smem_u32(const void* p) {
    uint32_t a;
    asm("{ .reg .u64 t; cvta.to.shared.u64 t, %1; cvt.u32.u64 %0, t; }" : "=r"(a) : "l"(p));
    return a;
}

__device__ __forceinline__ void ldsm_x4(uint32_t* r, uint32_t addr) {
    asm volatile("ldmatrix.sync.aligned.m8n8.x4.shared.b16 {%0,%1,%2,%3}, [%4];"
                 : "=r"(r[0]), "=r"(r[1]), "=r"(r[2]), "=r"(r[3]) : "r"(addr));
}

// fp16 inputs, fp32 accumulate
__device__ __forceinline__ void mma16816(float* c, const uint32_t* a, const uint32_t* b) {
    asm volatile(
        "mma.sync.aligned.m16n8k16.row.col.f32.f16.f16.f32 "
        "{%0,%1,%2,%3}, {%4,%5,%6,%7}, {%8,%9}, {%10,%11,%12,%13};"
        : "=f"(c[0]), "=f"(c[1]), "=f"(c[2]), "=f"(c[3])
        : "r"(a[0]), "r"(a[1]), "r"(a[2]), "r"(a[3]),
          "r"(b[0]), "r"(b[1]),
          "f"(c[0]), "f"(c[1]), "f"(c[2]), "f"(c[3]));
}

__device__ __forceinline__ uint32_t pack_h2(__half a, __half b) {
    return (uint32_t)__half_as_ushort(a) | ((uint32_t)__half_as_ushort(b) << 16);
}

// ---------------------------------------------------------------------------
// Fused: adj -> fp16 plane g_adj AND rowsum -> g_denom (+g_mask stash).
__global__ __launch_bounds__(256)
void splitrow_adj_kernel(const float* __restrict__ adj) {
    int row = blockIdx.x;
    int t = threadIdx.x;
    size_t base4 = (size_t)row * 256 + t;
    float4 v = ((const float4*)adj)[base4];
    uint2 hv;
    hv.x = pack_h2(__float2half_rn(v.x), __float2half_rn(v.y));
    hv.y = pack_h2(__float2half_rn(v.z), __float2half_rn(v.w));
    ((uint2*)g_adj)[base4] = hv;

    float s = (v.x + v.y) + (v.z + v.w);
    #pragma unroll
    for (int o = 16; o > 0; o >>= 1) s += __shfl_down_sync(0xffffffffu, s, o);
    __shared__ float sm[8];
    if ((t & 31) == 0) sm[t >> 5] = s;
    __syncthreads();
    if (t == 0) {
        float tot = 0.f;
        #pragma unroll
        for (int w = 0; w < 8; w++) tot += sm[w];
        g_denom[row] = tot + 1.0f;
        g_mask[row]  = tot;
    }
}

// colsum + mask finalize (only launched when mask is part of the output)
__global__ void colsum_mask_kernel(const float* __restrict__ adj) {
    int idx = blockIdx.x * blockDim.x + threadIdx.x;
    if (idx >= BN) return;
    int b = idx >> 10, n = idx & (NN - 1);
    const float* p = adj + (size_t)b * NN * NN + n;
    float c0 = 0.f, c1 = 0.f, c2 = 0.f, c3 = 0.f;
    #pragma unroll 4
    for (int m = 0; m < NN; m += 4) {
        c0 += p[(size_t)(m + 0) * NN];
        c1 += p[(size_t)(m + 1) * NN];
        c2 += p[(size_t)(m + 2) * NN];
        c3 += p[(size_t)(m + 3) * NN];
    }
    float cs = (c0 + c1) + (c2 + c3);
    g_mask[idx] = ((g_mask[idx] + cs) == 0.0f) ? 1.0f : 0.0f;
}

// W f32 -> g_W fp16 plane
__global__ void split_W_kernel(const float* __restrict__ in) {
    size_t i = (size_t)blockIdx.x * blockDim.x + threadIdx.x;
    if (i >= (size_t)DD * DD / 4) return;
    float4 v = ((const float4*)in)[i];
    uint2 hv;
    hv.x = pack_h2(__float2half_rn(v.x), __float2half_rn(v.y));
    hv.y = pack_h2(__float2half_rn(v.z), __float2half_rn(v.w));
    ((uint2*)g_W)[i] = hv;
}

// X [B][1024 k][512 n] f32 -> g_Xt [B][512 n][1024 k] fp16 (transpose, scaled)
__global__ void tsplit_kernel(const float* __restrict__ inExt, int use_internal,
                              float scale) {
    const float* in = use_internal ? g_X : inExt;
    __shared__ float tile[32][33];
    int b = blockIdx.z;
    int k0 = blockIdx.x * 32, n0 = blockIdx.y * 32;
    const float* src = in + (size_t)b * NN * DD;
    int tx = threadIdx.x, ty = threadIdx.y;     // (32, 8)
    #pragma unroll
    for (int r = 0; r < 4; r++)
        tile[ty + r * 8][tx] = src[(size_t)(k0 + ty + r * 8) * DD + n0 + tx];
    __syncthreads();
    __half* oh = g_Xt + (size_t)b * DD * NN;
    #pragma unroll
    for (int r = 0; r < 4; r++) {
        int n = n0 + ty + r * 8;
        oh[(size_t)n * NN + k0 + tx] = __float2half_rn(tile[tx][ty + r * 8] * scale);
    }
}

// ---------------------------------------------------------------------------
// Single-pass fp16 tensor-core GEMM.
// mode 0 (gemm1): D = adj @ Xt^T ; S = D*invscale + res -> g_S fp16 (x outscale)
// mode 1 (gemm2): D = S @ W^T    ; g_X = relu((D*invscale + 2b)/denom)  f32
// CTA 128x128, K-chunk 32, 8 warps (64x32 warp tile), reg-prefetch staging.
#define STRIDE 40
#define STEP   (16 * STRIDE * 2)    // 1280 bytes per 16-row block

__global__ __launch_bounds__(256)
void mma_gemm_kernel(int mode, const float* __restrict__ resExt, int res_internal,
                     const float* __restrict__ bias, float invscale, float outscale) {
    __shared__ __align__(16) __half sA[128 * STRIDE];
    __shared__ __align__(16) __half sB[128 * STRIDE];

    int tid = threadIdx.x, wid = tid >> 5, lane = tid & 31;
    int wm = (wid >> 2) * 64, wn = (wid & 3) * 32;
    int grp = lane >> 2, qid = lane & 3;

    const int K = (mode == 0) ? NN : DD;
    const int nchunks = K / 32;
    const int b = blockIdx.z;
    const int grow0 = (blockIdx.z * gridDim.y + blockIdx.y) * 128;
    const int col0 = blockIdx.x * 128;

    const __half *A, *B;
    int lda, ldb;
    if (mode == 0) {
        A = g_adj + (size_t)b * NN * NN + (size_t)(blockIdx.y * 128) * NN;  lda = NN;
        B = g_Xt  + (size_t)b * DD * NN + (size_t)col0 * NN;                ldb = NN;
    } else {
        A = g_S + (size_t)grow0 * DD;   lda = DD;
        B = g_W + (size_t)col0 * DD;    ldb = DD;
    }

    // staging: thread owns (row = tid/2, 16-half chunk = tid%2)
    const int lrow = tid >> 1;
    const int lcol = (tid & 1) * 16;
    const __half* gA = A + (size_t)lrow * lda + lcol;
    const __half* gB = B + (size_t)lrow * ldb + lcol;

    // ldmatrix per-thread offsets
    const int mat = lane >> 3, rr = lane & 7;
    const uint32_t offA = (uint32_t)(((wm + (mat & 1) * 8 + rr) * STRIDE + (mat >> 1) * 8) * 2);
    const uint32_t offB = (uint32_t)(((wn + (mat >> 1) * 8 + rr) * STRIDE + (mat & 1) * 8) * 2);
    const uint32_t sAb = smem_u32(sA);
    const uint32_t sBb = smem_u32(sB);

    float acc[4][4][4];
    #pragma unroll
    for (int i = 0; i < 4; i++)
        #pragma unroll
        for (int j = 0; j < 4; j++)
            #pragma unroll
            for (int q = 0; q < 4; q++) acc[i][j][q] = 0.f;

    uint4 p0 = *(const uint4*)gA, p1 = *(const uint4*)(gA + 8);
    uint4 p2 = *(const uint4*)gB, p3 = *(const uint4*)(gB + 8);

    for (int ci = 0; ci < nchunks; ci++) {
        __syncthreads();
        *(uint4*)&sA[lrow * STRIDE + lcol]     = p0;
        *(uint4*)&sA[lrow * STRIDE + lcol + 8] = p1;
        *(uint4*)&sB[lrow * STRIDE + lcol]     = p2;
        *(uint4*)&sB[lrow * STRIDE + lcol + 8] = p3;
        __syncthreads();

        if (ci + 1 < nchunks) {
            int k0 = (ci + 1) * 32;
            p0 = *(const uint4*)(gA + k0); p1 = *(const uint4*)(gA + k0 + 8);
            p2 = *(const uint4*)(gB + k0); p3 = *(const uint4*)(gB + k0 + 8);
        }

        #pragma unroll
        for (int ks = 0; ks < 2; ks++) {
            const uint32_t kof = (uint32_t)(ks * 32);
            uint32_t a[4][4], bb[8];
            #pragma unroll
            for (int mi = 0; mi < 4; mi++)
                ldsm_x4(a[mi], sAb + offA + mi * STEP + kof);
            ldsm_x4(bb,     sBb + offB + kof);
            ldsm_x4(bb + 4, sBb + offB + STEP + kof);
            #pragma unroll
            for (int mi = 0; mi < 4; mi++)
                #pragma unroll
                for (int ni = 0; ni < 4; ni++)
                    mma16816(acc[mi][ni], a[mi], &bb[ni * 2]);
        }
    }

    // Epilogue. Thread owns (rows grp, grp+8) x (cols qid*2, +1) per (mi,ni) tile.
    #pragma unroll
    for (int mi = 0; mi < 4; mi++) {
        #pragma unroll
        for (int h = 0; h < 2; h++) {
            int grow = grow0 + wm + mi * 16 + grp + h * 8;
            if (mode == 0) {
                const float* rbase = res_internal ? g_X : resExt;
                #pragma unroll
                for (int ni = 0; ni < 4; ni++) {
                    int gcol = col0 + wn + ni * 8 + qid * 2;
                    float2 res = *(const float2*)&rbase[(size_t)grow * DD + gcol];
                    float v0 = (acc[mi][ni][h * 2 + 0] * invscale + res.x) * outscale;
                    float v1 = (acc[mi][ni][h * 2 + 1] * invscale + res.y) * outscale;
                    *(uint32_t*)&g_S[(size_t)grow * DD + gcol] =
                        pack_h2(__float2half_rn(v0), __float2half_rn(v1));
                }
            } else {
                float rden = invscale / g_denom[grow];
                #pragma unroll
                for (int ni = 0; ni < 4; ni++) {
                    int gcol = col0 + wn + ni * 8 + qid * 2;
                    float2 bi = *(const float2*)&bias[gcol];
                    float2 o;
                    o.x = fmaxf((acc[mi][ni][h * 2 + 0] * invscale + 2.0f * bi.x) / g_denom[grow], 0.0f);
                    o.y = fmaxf((acc[mi][ni][h * 2 + 1] * invscale + 2.0f * bi.y) / g_denom[grow], 0.0f);
                    (void)rden;
                    o.x = fmaxf(o.x, 0.0f);
                    o.y = fmaxf(o.y, 0.0f);
                    *(float2*)&g_X[(size_t)grow * DD + gcol] = o;
                }
            }
        }
    }
}

// ---------------------------------------------------------------------------
// LayerNorm over last dim (512), one block (128 threads) per row, g_X -> out
__global__ void ln_kernel(const float* __restrict__ gamma,
                          const float* __restrict__ beta,
                          float* __restrict__ out) {
    int row = blockIdx.x;
    int t   = threadIdx.x;
    const float* p = g_X + (size_t)row * DD;
    float4 v = *(const float4*)&p[t * 4];

    __shared__ float sm[4];
    __shared__ float s_mu, s_rstd;

    float s = v.x + v.y + v.z + v.w;
    #pragma unroll
    for (int o = 16; o > 0; o >>= 1) s += __shfl_down_sync(0xffffffffu, s, o);
    if ((t & 31) == 0) sm[t >> 5] = s;
    __syncthreads();
    if (t == 0) s_mu = (sm[0] + sm[1] + sm[2] + sm[3]) * (1.0f / DD);
    __syncthreads();

    float mu = s_mu;
    float dx = v.x - mu, dy = v.y - mu, dz = v.z - mu, dw = v.w - mu;
    float q = dx * dx + dy * dy + dz * dz + dw * dw;
    #pragma unroll
    for (int o = 16; o > 0; o >>= 1) q += __shfl_down_sync(0xffffffffu, q, o);
    if ((t & 31) == 0) sm[t >> 5] = q;
    __syncthreads();
    if (t == 0)
        s_rstd = rsqrtf((sm[0] + sm[1] + sm[2] + sm[3]) * (1.0f / DD) + LN_EPS);
    __syncthreads();

    float r = s_rstd;
    float4 ga = *(const float4*)&gamma[t * 4];
    float4 be = *(const float4*)&beta[t * 4];
    float4 o;
    o.x = dx * r * ga.x + be.x;
    o.y = dy * r * ga.y + be.y;
    o.z = dz * r * ga.z + be.z;
    o.w = dw * r * ga.w + be.w;
    *(float4*)&out[(size_t)row * DD + t * 4] = o;
}

__global__ void mask_out_kernel(float* __restrict__ out, int count) {
    int i = blockIdx.x * blockDim.x + threadIdx.x;
    if (i < count) out[(size_t)OUT_ELEMS + i] = (i < BN) ? g_mask[i] : 0.0f;
}

// ---------------------------------------------------------------------------
extern "C" void kernel_launch(void* const* d_in, const int* in_sizes, int n_in,
                              void* d_out, int out_size) {
    const float* adj = (const float*)d_in[0];
    const float* x0  = (const float*)d_in[1];
    const float* W0w = (const float*)d_in[3];
    const float* W0b = (const float*)d_in[4];
    const float* W1w = (const float*)d_in[5];
    const float* W1b = (const float*)d_in[6];
    const float* lng = (const float*)d_in[7];
    const float* lnb = (const float*)d_in[8];
    float* out = (float*)d_out;
    int tail = out_size - OUT_ELEMS;

    // adj -> fp16 plane + rowsum/denom
    splitrow_adj_kernel<<<BN, 256>>>(adj);
    if (tail > 0)   // mask only needed when it is part of the output
        colsum_mask_kernel<<<BN / 256, 256>>>(adj);

    dim3 tgrid(NN / 32, DD / 32, BB), tblk(32, 8);
    tsplit_kernel<<<tgrid, tblk>>>(x0, 0, 1.0f);
    split_W_kernel<<<(DD * DD / 4 + 255) / 256, 256>>>(W0w);

    dim3 grid1(DD / 128, NN / 128, BB);     // 4 x 8 x 32
    dim3 grid2(DD / 128, BN / 128, 1);      // 4 x 256

    // Layer 0   (S magnitudes ~O(20): store unscaled)
    mma_gemm_kernel<<<grid1, 256>>>(0, x0, 0, nullptr, 1.0f, 1.0f);
    mma_gemm_kernel<<<grid2, 256>>>(1, nullptr, 0, W0b, 1.0f, 1.0f);

    // Layer 1 (activations ~0.036 rms: pre-scale X by 2^10; S ~O(1): unscaled)
    tsplit_kernel<<<tgrid, tblk>>>(nullptr, 1, L2SCALE);
    split_W_kernel<<<(DD * DD / 4 + 255) / 256, 256>>>(W1w);
    mma_gemm_kernel<<<grid1, 256>>>(0, nullptr, 1, nullptr, 1.0f / L2SCALE, 1.0f);
    mma_gemm_kernel<<<grid2, 256>>>(1, nullptr, 0, W1b, 1.0f, 1.0f);

    // LayerNorm -> output
    ln_kernel<<<BN, 128>>>(lng, lnb, out);

    if (tail > 0)
        mask_out_kernel<<<(tail + 255) / 256, 256>>>(out, tail);
}